// round 2
// baseline (speedup 1.0000x reference)
#include <cuda_runtime.h>
#include <math.h>

#define BB 2
#define TT 2048
#define DD 2048
#define HH 16
#define DHD 128
#define DC 384
#define NROWS (BB*TT)        // 4096
#define NC 32
#define CL (TT/NC)           // 64

// ---------------- scratch (device globals: no runtime allocation allowed) ----
__device__ float g_q[NROWS*DD];
__device__ float g_k[NROWS*DD];
__device__ float g_v[NROWS*DD];
__device__ float g_p[NROWS*DD];
__device__ float g_g[NROWS*DD];
__device__ float g_att[NROWS*DD];
__device__ float g_clockbuf[NROWS*HH];
__device__ float g_pmax[BB*HH*DHD];
__device__ float g_part_pm[BB*HH*NC*DHD];
__device__ float g_part_ps[BB*HH*NC*DHD];
__device__ float g_part_gs[BB*HH*NC*DHD];
__device__ float g_part_cs[BB*HH*NC*DHD];
__device__ float g_qcat[(size_t)NROWS*HH*DC];
__device__ float g_kcat[(size_t)NROWS*HH*DC];

__device__ __forceinline__ float softplus_f(float x) {
    // jax.nn.softplus = logaddexp(x, 0)
    return fmaxf(x, 0.f) + log1pf(expf(-fabsf(x)));
}

// ---------------- SGEMM: C[M,N] = A[M,K] @ B[K,N], all row-major ------------
// 128x128 block, BK=8, 256 threads, 8x8 per-thread micro-tile.
__global__ void __launch_bounds__(256) sgemm128(
    const float* __restrict__ A, const float* __restrict__ Bm,
    float* __restrict__ C, int M, int N, int K)
{
    __shared__ float As[8][128];
    __shared__ float Bs[8][128];
    int tid = threadIdx.x;
    int bx = blockIdx.x, by = blockIdx.y;

    const float* Ab = A + (size_t)by * 128 * K;
    const float* Bb = Bm + (size_t)bx * 128;

    int arow = tid >> 1, acol = (tid & 1) * 4;
    int brow = tid >> 5, bcol = (tid & 31) * 4;
    int ty = tid >> 4, tx = tid & 15;

    float acc[8][8];
#pragma unroll
    for (int i = 0; i < 8; i++)
#pragma unroll
        for (int j = 0; j < 8; j++) acc[i][j] = 0.f;

    for (int k0 = 0; k0 < K; k0 += 8) {
        float4 a4 = *(const float4*)(Ab + (size_t)arow * K + k0 + acol);
        As[acol + 0][arow] = a4.x;
        As[acol + 1][arow] = a4.y;
        As[acol + 2][arow] = a4.z;
        As[acol + 3][arow] = a4.w;
        float4 b4 = *(const float4*)(Bb + (size_t)(k0 + brow) * N + bcol);
        *(float4*)&Bs[brow][bcol] = b4;
        __syncthreads();
#pragma unroll
        for (int kk = 0; kk < 8; kk++) {
            float ra[8], rb[8];
            *(float4*)&ra[0] = *(const float4*)&As[kk][ty * 8];
            *(float4*)&ra[4] = *(const float4*)&As[kk][ty * 8 + 4];
            *(float4*)&rb[0] = *(const float4*)&Bs[kk][tx * 8];
            *(float4*)&rb[4] = *(const float4*)&Bs[kk][tx * 8 + 4];
#pragma unroll
            for (int i = 0; i < 8; i++)
#pragma unroll
                for (int j = 0; j < 8; j++)
                    acc[i][j] = fmaf(ra[i], rb[j], acc[i][j]);
        }
        __syncthreads();
    }
#pragma unroll
    for (int i = 0; i < 8; i++) {
        float* cp = C + (size_t)(by * 128 + ty * 8 + i) * N + bx * 128 + tx * 8;
        *(float4*)cp = make_float4(acc[i][0], acc[i][1], acc[i][2], acc[i][3]);
        *(float4*)(cp + 4) = make_float4(acc[i][4], acc[i][5], acc[i][6], acc[i][7]);
    }
}

// ---------------- clock = softplus(x @ W_clock) + 1e-6 ----------------------
__global__ void __launch_bounds__(128) clock_kernel(
    const float* __restrict__ x, const float* __restrict__ Wc)
{
    __shared__ float xs[DD];
    __shared__ float red[128];
    int n = blockIdx.x;
    for (int i = threadIdx.x; i < DD; i += 128) xs[i] = x[(size_t)n * DD + i];
    __syncthreads();
    int col = threadIdx.x >> 3, seg = threadIdx.x & 7;
    float s = 0.f;
    int k0 = seg * 256;
    for (int k = k0; k < k0 + 256; k++) s = fmaf(xs[k], Wc[k * HH + col], s);
    red[threadIdx.x] = s;
    __syncthreads();
    if (threadIdx.x < 16) {
        float t = 0.f;
        for (int j = 0; j < 8; j++) t += red[threadIdx.x * 8 + j];
        g_clockbuf[n * HH + threadIdx.x] = softplus_f(t) + 1e-6f;
    }
}

// ---------------- scan phase 1: per-chunk partials ---------------------------
__global__ void __launch_bounds__(128) scan_phase1()
{
    int c = blockIdx.x, bh = blockIdx.y, d = threadIdx.x;
    int b = bh >> 4, h = bh & 15;
    float pmax = -INFINITY, psum = 0.f, gsum = 0.f, csum = 0.f;
    for (int t = c * CL; t < (c + 1) * CL; t++) {
        int n = b * TT + t;
        float ck = g_clockbuf[n * HH + h];
        size_t idx = (size_t)n * DD + h * DHD + d;
        float pv = g_p[idx] + logf(ck);
        if (pv > pmax) { psum = psum * expf(pmax - pv) + 1.f; pmax = pv; }
        else psum += expf(pv - pmax);
        gsum += -softplus_f(g_g[idx]) * ck;
        csum += ck;
    }
    int o = (bh * NC + c) * DHD + d;
    g_part_pm[o] = pmax; g_part_ps[o] = psum;
    g_part_gs[o] = gsum; g_part_cs[o] = csum;
}

// ---------------- scan phase 2: global max + exclusive chunk prefixes --------
__global__ void __launch_bounds__(128) scan_phase2()
{
    int bh = blockIdx.x, d = threadIdx.x;
    float gmax = -INFINITY;
    for (int c = 0; c < NC; c++)
        gmax = fmaxf(gmax, g_part_pm[(bh * NC + c) * DHD + d]);
    g_pmax[bh * DHD + d] = gmax;
    float ep = 0.f, eg = 0.f, ec = 0.f;
    for (int c = 0; c < NC; c++) {
        int o = (bh * NC + c) * DHD + d;
        float pm = g_part_pm[o], ps = g_part_ps[o];
        float gs = g_part_gs[o], cs = g_part_cs[o];
        g_part_ps[o] = ep; g_part_gs[o] = eg; g_part_cs[o] = ec;
        ep += ps * expf(pm - gmax);
        eg += gs;
        ec += cs;
    }
}

// ---------------- scan phase 3: cumsums + RoPE + build q_cat/k_cat -----------
__global__ void __launch_bounds__(128) scan_phase3()
{
    int c = blockIdx.x, bh = blockIdx.y, d = threadIdx.x;
    int b = bh >> 4, h = bh & 15;
    int o = (bh * NC + c) * DHD + d;
    float gmax = g_pmax[bh * DHD + d];
    float pcs = g_part_ps[o], gcs = g_part_gs[o], ccs = g_part_cs[o];
    int fi = d & 63;
    float invf = expf(-(float)fi * (logf(10000.f) / 64.f));
    float sgn = (d & 1) ? 1.f : -1.f;
    const float scale = rsqrtf(384.f);
    for (int t = c * CL; t < (c + 1) * CL; t++) {
        int n = b * TT + t;
        float ck = g_clockbuf[n * HH + h];
        size_t idx = (size_t)n * DD + h * DHD + d;
        float pe = expf(g_p[idx] + logf(ck) - gmax);
        pcs += pe;
        gcs += -softplus_f(g_g[idx]) * ck;
        float gcp = expf(fminf(fmaxf(gcs, -50.f), 40.f));
        ccs += ck;
        float sn_, cs_;
        sincosf((float)t * invf, &sn_, &cs_);
        float qv = g_q[idx], kv = g_k[idx];
        float qp = __shfl_xor_sync(0xffffffffu, qv, 1);
        float kp = __shfl_xor_sync(0xffffffffu, kv, 1);
        float qr = qv * cs_ + sgn * qp * sn_;
        float kr = kv * cs_ + sgn * kp * sn_;
        size_t co = ((size_t)n * HH + h) * DC + d;
        g_qcat[co]           = scale * qr / (pcs + 1e-8f);
        g_qcat[co + DHD]     = scale * qr * gcp;
        g_qcat[co + 2*DHD]   = scale * qr / ccs;
        g_kcat[co]           = kr * pe;
        g_kcat[co + DHD]     = kr / (gcp + 1e-8f);
        g_kcat[co + 2*DHD]   = kr * ck;
    }
}

// ---------------- flash attention (non-causal), fp32 -------------------------
// block: 256 threads, 64 queries x 32-key tiles, K-dim = 384.
// thread layout: tyq = tid>>3 (32 query pairs), txk = tid&7 (8 key quads / dv16)
#define ATT_SMEM_FLOATS (384*64 + 384*32 + 32*128 + 32*64)
__global__ void __launch_bounds__(256) att_kernel()
{
    extern __shared__ float sm[];
    float* sQ = sm;                 // [384][64]
    float* sK = sQ + 384 * 64;      // [384][32]
    float* sV = sK + 384 * 32;      // [32][128]
    float* sP = sV + 32 * 128;      // [32][64]

    int tid = threadIdx.x;
    int tq0 = blockIdx.x * 64;
    int bh = blockIdx.y;
    int b = bh >> 4, h = bh & 15;
    int tyq = tid >> 3, txk = tid & 7;

    // load Q tile (transposed: sQ[c][q])
    for (int l = tid; l < 64 * 384; l += 256) {
        int q = l / 384, c = l - q * 384;
        sQ[c * 64 + q] = g_qcat[((size_t)(b * TT + tq0 + q) * HH + h) * DC + c];
    }
    __syncthreads();

    float m[2] = { -INFINITY, -INFINITY };
    float lsum[2] = { 0.f, 0.f };
    float acc[2][16];
#pragma unroll
    for (int i = 0; i < 2; i++)
#pragma unroll
        for (int j = 0; j < 16; j++) acc[i][j] = 0.f;

    for (int s0 = 0; s0 < TT; s0 += 32) {
        // load K tile (transposed) + V tile
        for (int l4 = tid; l4 < 32 * 96; l4 += 256) {
            int s = l4 / 96, c4 = (l4 - s * 96) * 4;
            float4 kv = *(const float4*)&g_kcat[((size_t)(b * TT + s0 + s) * HH + h) * DC + c4];
            sK[(c4 + 0) * 32 + s] = kv.x;
            sK[(c4 + 1) * 32 + s] = kv.y;
            sK[(c4 + 2) * 32 + s] = kv.z;
            sK[(c4 + 3) * 32 + s] = kv.w;
        }
        for (int l4 = tid; l4 < 32 * 32; l4 += 256) {
            int s = l4 >> 5, d4 = (l4 & 31) * 4;
            *(float4*)&sV[s * 128 + d4] =
                *(const float4*)&g_v[(size_t)(b * TT + s0 + s) * DD + h * DHD + d4];
        }
        __syncthreads();

        // scores: 2 queries x 4 keys per thread over K=384
        float sc[2][4];
#pragma unroll
        for (int i = 0; i < 2; i++)
#pragma unroll
            for (int j = 0; j < 4; j++) sc[i][j] = 0.f;
        for (int cc = 0; cc < 384; cc++) {
            float2 qv = *(const float2*)(sQ + cc * 64 + 2 * tyq);
            float4 kv = *(const float4*)(sK + cc * 32 + 4 * txk);
            sc[0][0] = fmaf(qv.x, kv.x, sc[0][0]);
            sc[0][1] = fmaf(qv.x, kv.y, sc[0][1]);
            sc[0][2] = fmaf(qv.x, kv.z, sc[0][2]);
            sc[0][3] = fmaf(qv.x, kv.w, sc[0][3]);
            sc[1][0] = fmaf(qv.y, kv.x, sc[1][0]);
            sc[1][1] = fmaf(qv.y, kv.y, sc[1][1]);
            sc[1][2] = fmaf(qv.y, kv.z, sc[1][2]);
            sc[1][3] = fmaf(qv.y, kv.w, sc[1][3]);
        }

        // online softmax update per query row (reduce over 8 txk lanes)
#pragma unroll
        for (int i = 0; i < 2; i++) {
            float mt = fmaxf(fmaxf(sc[i][0], sc[i][1]), fmaxf(sc[i][2], sc[i][3]));
            mt = fmaxf(mt, __shfl_xor_sync(0xffffffffu, mt, 1));
            mt = fmaxf(mt, __shfl_xor_sync(0xffffffffu, mt, 2));
            mt = fmaxf(mt, __shfl_xor_sync(0xffffffffu, mt, 4));
            float mn = fmaxf(m[i], mt);
            float corr = expf(m[i] - mn);
            float ls = 0.f;
#pragma unroll
            for (int j = 0; j < 4; j++) {
                float p = expf(sc[i][j] - mn);
                sP[(4 * txk + j) * 64 + 2 * tyq + i] = p;
                ls += p;
            }
            ls += __shfl_xor_sync(0xffffffffu, ls, 1);
            ls += __shfl_xor_sync(0xffffffffu, ls, 2);
            ls += __shfl_xor_sync(0xffffffffu, ls, 4);
            lsum[i] = lsum[i] * corr + ls;
            m[i] = mn;
#pragma unroll
            for (int j = 0; j < 16; j++) acc[i][j] *= corr;
        }
        __syncthreads();

        // PV: thread owns (2 queries) x (16 output dims at txk*16)
        for (int k = 0; k < 32; k++) {
            float2 pv = *(const float2*)(sP + k * 64 + 2 * tyq);
            const float4* vp = (const float4*)(sV + k * 128 + txk * 16);
#pragma unroll
            for (int j = 0; j < 4; j++) {
                float4 vv = vp[j];
                acc[0][4 * j + 0] = fmaf(pv.x, vv.x, acc[0][4 * j + 0]);
                acc[0][4 * j + 1] = fmaf(pv.x, vv.y, acc[0][4 * j + 1]);
                acc[0][4 * j + 2] = fmaf(pv.x, vv.z, acc[0][4 * j + 2]);
                acc[0][4 * j + 3] = fmaf(pv.x, vv.w, acc[0][4 * j + 3]);
                acc[1][4 * j + 0] = fmaf(pv.y, vv.x, acc[1][4 * j + 0]);
                acc[1][4 * j + 1] = fmaf(pv.y, vv.y, acc[1][4 * j + 1]);
                acc[1][4 * j + 2] = fmaf(pv.y, vv.z, acc[1][4 * j + 2]);
                acc[1][4 * j + 3] = fmaf(pv.y, vv.w, acc[1][4 * j + 3]);
            }
        }
        __syncthreads();
    }

#pragma unroll
    for (int i = 0; i < 2; i++) {
        int tglob = tq0 + 2 * tyq + i;
        float inv = 1.f / lsum[i];
        float* outp = g_att + (size_t)(b * TT + tglob) * DD + h * DHD + txk * 16;
#pragma unroll
        for (int j = 0; j < 4; j++) {
            float4 w = make_float4(acc[i][4 * j + 0] * inv, acc[i][4 * j + 1] * inv,
                                   acc[i][4 * j + 2] * inv, acc[i][4 * j + 3] * inv);
            ((float4*)outp)[j] = w;
        }
    }
}

// ---------------- launch ----------------------------------------------------
extern "C" void kernel_launch(void* const* d_in, const int* in_sizes, int n_in,
                              void* d_out, int out_size)
{
    const float* x   = (const float*)d_in[0];
    const float* Wq  = (const float*)d_in[1];
    const float* Wk  = (const float*)d_in[2];
    const float* Wv  = (const float*)d_in[3];
    const float* Wg  = (const float*)d_in[4];
    const float* Wp  = (const float*)d_in[5];
    const float* Wcl = (const float*)d_in[6];
    const float* Wc  = (const float*)d_in[7];
    float* out = (float*)d_out;

    float *pq, *pk, *pv, *pp, *pg, *patt;
    cudaGetSymbolAddress((void**)&pq,  g_q);
    cudaGetSymbolAddress((void**)&pk,  g_k);
    cudaGetSymbolAddress((void**)&pv,  g_v);
    cudaGetSymbolAddress((void**)&pp,  g_p);
    cudaGetSymbolAddress((void**)&pg,  g_g);
    cudaGetSymbolAddress((void**)&patt, g_att);

    dim3 ggrid(DD / 128, NROWS / 128);  // (16, 32)
    sgemm128<<<ggrid, 256>>>(x, Wq, pq, NROWS, DD, DD);
    sgemm128<<<ggrid, 256>>>(x, Wk, pk, NROWS, DD, DD);
    sgemm128<<<ggrid, 256>>>(x, Wv, pv, NROWS, DD, DD);
    sgemm128<<<ggrid, 256>>>(x, Wp, pp, NROWS, DD, DD);
    sgemm128<<<ggrid, 256>>>(x, Wg, pg, NROWS, DD, DD);
    clock_kernel<<<NROWS, 128>>>(x, Wcl);

    scan_phase1<<<dim3(NC, BB * HH), 128>>>();
    scan_phase2<<<BB * HH, 128>>>();
    scan_phase3<<<dim3(NC, BB * HH), 128>>>();

    cudaFuncSetAttribute(att_kernel, cudaFuncAttributeMaxDynamicSharedMemorySize,
                         ATT_SMEM_FLOATS * (int)sizeof(float));
    att_kernel<<<dim3(TT / 64, BB * HH), 256, ATT_SMEM_FLOATS * sizeof(float)>>>();

    sgemm128<<<ggrid, 256>>>(patt, Wc, out, NROWS, DD, DD);
}

// round 3
// speedup vs baseline: 1.9429x; 1.9429x over previous
#include <cuda_runtime.h>
#include <math.h>

#define BB 2
#define TT 2048
#define DD 2048
#define HH 16
#define DHD 128
#define DC 384
#define NROWS (BB*TT)        // 4096
#define NC 32
#define CL (TT/NC)           // 64

// ---------------- scratch (device globals: no runtime allocation allowed) ----
__device__ float g_q[NROWS*DD];
__device__ float g_k[NROWS*DD];
__device__ float g_v[NROWS*DD];
__device__ float g_p[NROWS*DD];
__device__ float g_g[NROWS*DD];
__device__ float g_att[NROWS*DD];
__device__ float g_clockbuf[NROWS*HH];
__device__ float g_logclock[NROWS*HH];
__device__ float g_pmax[BB*HH*DHD];
__device__ float g_part_pm[BB*HH*NC*DHD];
__device__ float g_part_ps[BB*HH*NC*DHD];
__device__ float g_part_gs[BB*HH*NC*DHD];
__device__ float g_part_cs[BB*HH*NC*DHD];
__device__ float g_qcat[(size_t)NROWS*HH*DC];
__device__ float g_kcat[(size_t)NROWS*HH*DC];
__device__ float g_qT[(size_t)BB*HH*DC*TT];   // [bh][c][t]
__device__ float g_kT[(size_t)BB*HH*DC*TT];

__device__ __forceinline__ float softplus_f(float x) {
    return fmaxf(x, 0.f) + log1pf(expf(-fabsf(x)));
}
__device__ __forceinline__ float softplus_fast(float x) {
    return fmaxf(x, 0.f) + __logf(1.f + __expf(-fabsf(x)));
}

// ---------------- SGEMM: C[M,N] = A[M,K] @ B[K,N], row-major, double-buffered
__global__ void __launch_bounds__(256, 2) sgemm128(
    const float* __restrict__ A, const float* __restrict__ Bm,
    float* __restrict__ C, int M, int N, int K)
{
    __shared__ float As[2][8][128];
    __shared__ float Bs[2][8][128];
    int tid = threadIdx.x;
    int bx = blockIdx.x, by = blockIdx.y;

    const float* Ab = A + (size_t)by * 128 * K;
    const float* Bb = Bm + (size_t)bx * 128;

    int arow = tid >> 1, acol = (tid & 1) * 4;
    int brow = tid >> 5, bcol = (tid & 31) * 4;
    int ty = tid >> 4, tx = tid & 15;

    float acc[8][8];
#pragma unroll
    for (int i = 0; i < 8; i++)
#pragma unroll
        for (int j = 0; j < 8; j++) acc[i][j] = 0.f;

    // preload k0 = 0
    {
        float4 a4 = *(const float4*)(Ab + (size_t)arow * K + acol);
        As[0][acol + 0][arow] = a4.x; As[0][acol + 1][arow] = a4.y;
        As[0][acol + 2][arow] = a4.z; As[0][acol + 3][arow] = a4.w;
        float4 b4 = *(const float4*)(Bb + (size_t)brow * N + bcol);
        *(float4*)&Bs[0][brow][bcol] = b4;
    }
    __syncthreads();

    int buf = 0;
    for (int k0 = 0; k0 < K; k0 += 8) {
        bool has_next = (k0 + 8 < K);
        float4 a4n, b4n;
        if (has_next) {
            a4n = *(const float4*)(Ab + (size_t)arow * K + k0 + 8 + acol);
            b4n = *(const float4*)(Bb + (size_t)(k0 + 8 + brow) * N + bcol);
        }
#pragma unroll
        for (int kk = 0; kk < 8; kk++) {
            float ra[8], rb[8];
            *(float4*)&ra[0] = *(const float4*)&As[buf][kk][ty * 8];
            *(float4*)&ra[4] = *(const float4*)&As[buf][kk][ty * 8 + 4];
            *(float4*)&rb[0] = *(const float4*)&Bs[buf][kk][tx * 8];
            *(float4*)&rb[4] = *(const float4*)&Bs[buf][kk][tx * 8 + 4];
#pragma unroll
            for (int i = 0; i < 8; i++)
#pragma unroll
                for (int j = 0; j < 8; j++)
                    acc[i][j] = fmaf(ra[i], rb[j], acc[i][j]);
        }
        if (has_next) {
            int nb = buf ^ 1;
            As[nb][acol + 0][arow] = a4n.x; As[nb][acol + 1][arow] = a4n.y;
            As[nb][acol + 2][arow] = a4n.z; As[nb][acol + 3][arow] = a4n.w;
            *(float4*)&Bs[nb][brow][bcol] = b4n;
        }
        __syncthreads();
        buf ^= 1;
    }
#pragma unroll
    for (int i = 0; i < 8; i++) {
        float* cp = C + (size_t)(by * 128 + ty * 8 + i) * N + bx * 128 + tx * 8;
        *(float4*)cp = make_float4(acc[i][0], acc[i][1], acc[i][2], acc[i][3]);
        *(float4*)(cp + 4) = make_float4(acc[i][4], acc[i][5], acc[i][6], acc[i][7]);
    }
}

// ---------------- clock = softplus(x @ W_clock) + 1e-6, plus its log ---------
__global__ void __launch_bounds__(128) clock_kernel(
    const float* __restrict__ x, const float* __restrict__ Wc)
{
    __shared__ float xs[DD];
    __shared__ float red[128];
    int n = blockIdx.x;
    for (int i = threadIdx.x; i < DD; i += 128) xs[i] = x[(size_t)n * DD + i];
    __syncthreads();
    int col = threadIdx.x >> 3, seg = threadIdx.x & 7;
    float s = 0.f;
    int k0 = seg * 256;
    for (int k = k0; k < k0 + 256; k++) s = fmaf(xs[k], Wc[k * HH + col], s);
    red[threadIdx.x] = s;
    __syncthreads();
    if (threadIdx.x < 16) {
        float t = 0.f;
        for (int j = 0; j < 8; j++) t += red[threadIdx.x * 8 + j];
        float ck = softplus_f(t) + 1e-6f;
        g_clockbuf[n * HH + threadIdx.x] = ck;
        g_logclock[n * HH + threadIdx.x] = __logf(ck);
    }
}

// ---------------- scan phase 1: per-chunk partials ---------------------------
__global__ void __launch_bounds__(128) scan_phase1()
{
    int c = blockIdx.x, bh = blockIdx.y, d = threadIdx.x;
    int b = bh >> 4, h = bh & 15;
    float pmax = -INFINITY, psum = 0.f, gsum = 0.f, csum = 0.f;
    for (int t = c * CL; t < (c + 1) * CL; t++) {
        int n = b * TT + t;
        float ck = g_clockbuf[n * HH + h];
        float lck = g_logclock[n * HH + h];
        size_t idx = (size_t)n * DD + h * DHD + d;
        float pv = g_p[idx] + lck;
        if (pv > pmax) { psum = psum * __expf(pmax - pv) + 1.f; pmax = pv; }
        else psum += __expf(pv - pmax);
        gsum += -softplus_fast(g_g[idx]) * ck;
        csum += ck;
    }
    int o = (bh * NC + c) * DHD + d;
    g_part_pm[o] = pmax; g_part_ps[o] = psum;
    g_part_gs[o] = gsum; g_part_cs[o] = csum;
}

// ---------------- scan phase 2: global max + exclusive chunk prefixes --------
__global__ void __launch_bounds__(128) scan_phase2()
{
    int bh = blockIdx.x, d = threadIdx.x;
    float gmax = -INFINITY;
    for (int c = 0; c < NC; c++)
        gmax = fmaxf(gmax, g_part_pm[(bh * NC + c) * DHD + d]);
    g_pmax[bh * DHD + d] = gmax;
    float ep = 0.f, eg = 0.f, ec = 0.f;
    for (int c = 0; c < NC; c++) {
        int o = (bh * NC + c) * DHD + d;
        float pm = g_part_pm[o], ps = g_part_ps[o];
        float gs = g_part_gs[o], cs = g_part_cs[o];
        g_part_ps[o] = ep; g_part_gs[o] = eg; g_part_cs[o] = ec;
        ep += ps * __expf(pm - gmax);
        eg += gs;
        ec += cs;
    }
}

// ---------------- scan phase 3: cumsums + RoPE + build q_cat/k_cat -----------
__global__ void __launch_bounds__(128) scan_phase3()
{
    int c = blockIdx.x, bh = blockIdx.y, d = threadIdx.x;
    int b = bh >> 4, h = bh & 15;
    int o = (bh * NC + c) * DHD + d;
    float gmax = g_pmax[bh * DHD + d];
    float pcs = g_part_ps[o], gcs = g_part_gs[o], ccs = g_part_cs[o];
    int fi = d & 63;
    float invf = expf(-(float)fi * (logf(10000.f) / 64.f));
    float sgn = (d & 1) ? 1.f : -1.f;
    const float scale = rsqrtf(384.f);
    // incremental rotation: accurate sincos only twice
    float cs_, sn_, cd, sd;
    sincosf((float)(c * CL) * invf, &sn_, &cs_);
    sincosf(invf, &sd, &cd);
    for (int t = c * CL; t < (c + 1) * CL; t++) {
        int n = b * TT + t;
        float ck = g_clockbuf[n * HH + h];
        float lck = g_logclock[n * HH + h];
        size_t idx = (size_t)n * DD + h * DHD + d;
        float pe = __expf(g_p[idx] + lck - gmax);
        pcs += pe;
        gcs += -softplus_fast(g_g[idx]) * ck;
        float gcp = __expf(fminf(fmaxf(gcs, -50.f), 40.f));
        ccs += ck;
        float qv = g_q[idx], kv = g_k[idx];
        float qp = __shfl_xor_sync(0xffffffffu, qv, 1);
        float kp = __shfl_xor_sync(0xffffffffu, kv, 1);
        float qr = qv * cs_ + sgn * qp * sn_;
        float kr = kv * cs_ + sgn * kp * sn_;
        size_t co = ((size_t)n * HH + h) * DC + d;
        g_qcat[co]           = scale * qr / (pcs + 1e-8f);
        g_qcat[co + DHD]     = scale * qr * gcp;
        g_qcat[co + 2*DHD]   = scale * qr / ccs;
        g_kcat[co]           = kr * pe;
        g_kcat[co + DHD]     = kr / (gcp + 1e-8f);
        g_kcat[co + 2*DHD]   = kr * ck;
        // rotate (cos,sin) by invf
        float nc_ = cs_ * cd - sn_ * sd;
        float ns_ = sn_ * cd + cs_ * sd;
        cs_ = nc_; sn_ = ns_;
    }
}

// ---------------- transpose q_cat/k_cat: [n][h][c] -> [bh][c][t] -------------
__global__ void __launch_bounds__(256) transpose_cat(
    const float* __restrict__ src, float* __restrict__ dst)
{
    __shared__ float tl[32][33];
    int bh = blockIdx.z; int b = bh >> 4, h = bh & 15;
    int c0 = blockIdx.x * 32, t0 = blockIdx.y * 32;
    int xx = threadIdx.x, yy = threadIdx.y;
    for (int r = yy; r < 32; r += 8)
        tl[r][xx] = src[((size_t)(b * TT + t0 + r) * HH + h) * DC + c0 + xx];
    __syncthreads();
    for (int r = yy; r < 32; r += 8)
        dst[((size_t)bh * DC + c0 + r) * TT + t0 + xx] = tl[xx][r];
}

// ---------------- flash attention v2: 128q x 128s tiles, 8x8 micro-tiles -----
// smem: sP[128][128] (swizzled), sA[16][128] (Q chunk), sB[16][128] (K/V chunk)
#define ATT_SMEM_BYTES ((128*128 + 2*16*128) * 4)
__global__ void __launch_bounds__(256, 1) att2()
{
    extern __shared__ float sm[];
    float* sP = sm;                 // 128*128
    float* sA = sP + 128 * 128;     // 16*128
    float* sB = sA + 16 * 128;      // 16*128

    int tid = threadIdx.x;
    int ty = tid >> 4, tx = tid & 15;
    int tq0 = blockIdx.x * 128;
    int bh = blockIdx.y;
    int b = bh >> 4, h = bh & 15;

    const float* qTb = g_qT + (size_t)bh * DC * TT;
    const float* kTb = g_kT + (size_t)bh * DC * TT;
    const float* vb  = g_v + (size_t)(b * TT) * DD + h * DHD;

    float m[8], l[8], acc_o[8][8];
#pragma unroll
    for (int i = 0; i < 8; i++) {
        m[i] = -INFINITY; l[i] = 0.f;
#pragma unroll
        for (int j = 0; j < 8; j++) acc_o[i][j] = 0.f;
    }

    int cb = ((ty ^ tx) & 15) * 8;   // swizzled P column base for this thread

    for (int s0 = 0; s0 < TT; s0 += 128) {
        float acc_s[8][8];
#pragma unroll
        for (int i = 0; i < 8; i++)
#pragma unroll
            for (int j = 0; j < 8; j++) acc_s[i][j] = 0.f;

        // ---- scores: 128x128 over K-dim 384, chunks of 16 ----
        for (int kc = 0; kc < 24; kc++) {
            int c0 = kc * 16;
#pragma unroll
            for (int u = 0; u < 2; u++) {
                int f4 = tid + u * 256;
                int row = f4 >> 5, col4 = (f4 & 31) << 2;
                *(float4*)&sA[row * 128 + col4] =
                    *(const float4*)&qTb[(size_t)(c0 + row) * TT + tq0 + col4];
                *(float4*)&sB[row * 128 + col4] =
                    *(const float4*)&kTb[(size_t)(c0 + row) * TT + s0 + col4];
            }
            __syncthreads();
#pragma unroll
            for (int kk = 0; kk < 16; kk++) {
                float ra[8], rb[8];
                *(float4*)&ra[0] = *(const float4*)&sA[kk * 128 + ty * 8];
                *(float4*)&ra[4] = *(const float4*)&sA[kk * 128 + ty * 8 + 4];
                *(float4*)&rb[0] = *(const float4*)&sB[kk * 128 + tx * 8];
                *(float4*)&rb[4] = *(const float4*)&sB[kk * 128 + tx * 8 + 4];
#pragma unroll
                for (int i = 0; i < 8; i++)
#pragma unroll
                    for (int j = 0; j < 8; j++)
                        acc_s[i][j] = fmaf(ra[i], rb[j], acc_s[i][j]);
            }
            __syncthreads();
        }

        // ---- online softmax over rows (16 tx lanes share a row set) ----
#pragma unroll
        for (int i = 0; i < 8; i++) {
            float mt = acc_s[i][0];
#pragma unroll
            for (int j = 1; j < 8; j++) mt = fmaxf(mt, acc_s[i][j]);
            mt = fmaxf(mt, __shfl_xor_sync(0xffffffffu, mt, 1));
            mt = fmaxf(mt, __shfl_xor_sync(0xffffffffu, mt, 2));
            mt = fmaxf(mt, __shfl_xor_sync(0xffffffffu, mt, 4));
            mt = fmaxf(mt, __shfl_xor_sync(0xffffffffu, mt, 8));
            float mn = fmaxf(m[i], mt);
            float corr = __expf(m[i] - mn);
            float ls = 0.f;
#pragma unroll
            for (int j = 0; j < 8; j++) {
                float p = __expf(acc_s[i][j] - mn);
                acc_s[i][j] = p;
                ls += p;
            }
            ls += __shfl_xor_sync(0xffffffffu, ls, 1);
            ls += __shfl_xor_sync(0xffffffffu, ls, 2);
            ls += __shfl_xor_sync(0xffffffffu, ls, 4);
            ls += __shfl_xor_sync(0xffffffffu, ls, 8);
            l[i] = l[i] * corr + ls;
            m[i] = mn;
#pragma unroll
            for (int j = 0; j < 8; j++) acc_o[i][j] *= corr;
        }

        // ---- write P transposed + swizzled: sP[s][ q ^ (s & 0x78) ] ----
#pragma unroll
        for (int j = 0; j < 8; j++) {
            int srow = tx * 8 + j;
            *(float4*)&sP[srow * 128 + cb] =
                make_float4(acc_s[0][j], acc_s[1][j], acc_s[2][j], acc_s[3][j]);
            *(float4*)&sP[srow * 128 + cb + 4] =
                make_float4(acc_s[4][j], acc_s[5][j], acc_s[6][j], acc_s[7][j]);
        }
        __syncthreads();

        // ---- PV: out[128q][128d] += P[128q][128s] @ V[128s][128d] ----
        for (int kc2 = 0; kc2 < 8; kc2++) {
#pragma unroll
            for (int u = 0; u < 2; u++) {
                int f4 = tid + u * 256;
                int row = f4 >> 5, col4 = (f4 & 31) << 2;
                *(float4*)&sB[row * 128 + col4] =
                    *(const float4*)&vb[(size_t)(s0 + kc2 * 16 + row) * DD + col4];
            }
            __syncthreads();
#pragma unroll
            for (int kkl = 0; kkl < 16; kkl++) {
                int kk = kc2 * 16 + kkl;
                int qg = ((ty ^ (kk >> 3)) & 15) * 8;
                float ra[8], rb[8];
                *(float4*)&ra[0] = *(const float4*)&sP[kk * 128 + qg];
                *(float4*)&ra[4] = *(const float4*)&sP[kk * 128 + qg + 4];
                *(float4*)&rb[0] = *(const float4*)&sB[kkl * 128 + tx * 8];
                *(float4*)&rb[4] = *(const float4*)&sB[kkl * 128 + tx * 8 + 4];
#pragma unroll
                for (int i = 0; i < 8; i++)
#pragma unroll
                    for (int j = 0; j < 8; j++)
                        acc_o[i][j] = fmaf(ra[i], rb[j], acc_o[i][j]);
            }
            __syncthreads();
        }
    }

    // ---- epilogue ----
#pragma unroll
    for (int i = 0; i < 8; i++) {
        float inv = 1.f / l[i];
        int q = tq0 + ty * 8 + i;
        float* outp = g_att + (size_t)(b * TT + q) * DD + h * DHD + tx * 8;
        *(float4*)outp = make_float4(acc_o[i][0] * inv, acc_o[i][1] * inv,
                                     acc_o[i][2] * inv, acc_o[i][3] * inv);
        *(float4*)(outp + 4) = make_float4(acc_o[i][4] * inv, acc_o[i][5] * inv,
                                           acc_o[i][6] * inv, acc_o[i][7] * inv);
    }
}

// ---------------- launch ----------------------------------------------------
extern "C" void kernel_launch(void* const* d_in, const int* in_sizes, int n_in,
                              void* d_out, int out_size)
{
    const float* x   = (const float*)d_in[0];
    const float* Wq  = (const float*)d_in[1];
    const float* Wk  = (const float*)d_in[2];
    const float* Wv  = (const float*)d_in[3];
    const float* Wg  = (const float*)d_in[4];
    const float* Wp  = (const float*)d_in[5];
    const float* Wcl = (const float*)d_in[6];
    const float* Wc  = (const float*)d_in[7];
    float* out = (float*)d_out;

    float *pq, *pk, *pv, *pp, *pg, *patt, *pqc, *pkc, *pqT, *pkT;
    cudaGetSymbolAddress((void**)&pq,  g_q);
    cudaGetSymbolAddress((void**)&pk,  g_k);
    cudaGetSymbolAddress((void**)&pv,  g_v);
    cudaGetSymbolAddress((void**)&pp,  g_p);
    cudaGetSymbolAddress((void**)&pg,  g_g);
    cudaGetSymbolAddress((void**)&patt, g_att);
    cudaGetSymbolAddress((void**)&pqc, g_qcat);
    cudaGetSymbolAddress((void**)&pkc, g_kcat);
    cudaGetSymbolAddress((void**)&pqT, g_qT);
    cudaGetSymbolAddress((void**)&pkT, g_kT);

    dim3 ggrid(DD / 128, NROWS / 128);  // (16, 32)
    sgemm128<<<ggrid, 256>>>(x, Wq, pq, NROWS, DD, DD);
    sgemm128<<<ggrid, 256>>>(x, Wk, pk, NROWS, DD, DD);
    sgemm128<<<ggrid, 256>>>(x, Wv, pv, NROWS, DD, DD);
    sgemm128<<<ggrid, 256>>>(x, Wp, pp, NROWS, DD, DD);
    sgemm128<<<ggrid, 256>>>(x, Wg, pg, NROWS, DD, DD);
    clock_kernel<<<NROWS, 128>>>(x, Wcl);

    scan_phase1<<<dim3(NC, BB * HH), 128>>>();
    scan_phase2<<<BB * HH, 128>>>();
    scan_phase3<<<dim3(NC, BB * HH), 128>>>();

    dim3 tgrid(DC / 32, TT / 32, BB * HH);
    transpose_cat<<<tgrid, dim3(32, 8)>>>(pqc, pqT);
    transpose_cat<<<tgrid, dim3(32, 8)>>>(pkc, pkT);

    cudaFuncSetAttribute(att2, cudaFuncAttributeMaxDynamicSharedMemorySize,
                         ATT_SMEM_BYTES);
    att2<<<dim3(TT / 128, BB * HH), 256, ATT_SMEM_BYTES>>>();

    sgemm128<<<ggrid, 256>>>(patt, Wc, out, NROWS, DD, DD);
}

// round 6
// speedup vs baseline: 4.8929x; 2.5183x over previous
#include <cuda_runtime.h>
#include <cuda_bf16.h>
#include <math.h>
#include <stdint.h>

#define BB 2
#define TT 2048
#define DD 2048
#define HH 16
#define DHD 128
#define DC 384
#define NROWS (BB*TT)        // 4096
#define NC 32
#define CL (TT/NC)           // 64

// ---------------- scratch (device globals: no runtime allocation allowed) ----
__device__ float g_q[NROWS*DD];
__device__ float g_k[NROWS*DD];
__device__ float g_v[NROWS*DD];
__device__ float g_p[NROWS*DD];
__device__ float g_g[NROWS*DD];
__device__ float g_clockbuf[NROWS*HH];
__device__ float g_logclock[NROWS*HH];
__device__ float g_pmax[BB*HH*DHD];
__device__ float g_part_pm[BB*HH*NC*DHD];
__device__ float g_part_ps[BB*HH*NC*DHD];
__device__ float g_part_gs[BB*HH*NC*DHD];
__device__ float g_part_cs[BB*HH*NC*DHD];

// bf16 split operands
__device__ __align__(16) __nv_bfloat16 g_xh[(size_t)NROWS*DD];
__device__ __align__(16) __nv_bfloat16 g_xl[(size_t)NROWS*DD];
__device__ __align__(16) __nv_bfloat16 g_ah[(size_t)NROWS*DD];   // attention out hi
__device__ __align__(16) __nv_bfloat16 g_al[(size_t)NROWS*DD];   // attention out lo
__device__ __align__(16) __nv_bfloat16 g_vh[(size_t)NROWS*DD];
__device__ __align__(16) __nv_bfloat16 g_vl[(size_t)NROWS*DD];
__device__ __align__(16) __nv_bfloat16 g_wth[(size_t)6*DD*DD];   // W^T hi [N][K]
__device__ __align__(16) __nv_bfloat16 g_wtl[(size_t)6*DD*DD];   // W^T lo
__device__ __align__(16) __nv_bfloat16 g_qch[(size_t)NROWS*HH*DC];
__device__ __align__(16) __nv_bfloat16 g_qcl[(size_t)NROWS*HH*DC];
__device__ __align__(16) __nv_bfloat16 g_kch[(size_t)NROWS*HH*DC];
__device__ __align__(16) __nv_bfloat16 g_kcl[(size_t)NROWS*HH*DC];

__device__ __forceinline__ float softplus_f(float x) {
    return fmaxf(x, 0.f) + log1pf(expf(-fabsf(x)));
}
__device__ __forceinline__ float softplus_fast(float x) {
    return fmaxf(x, 0.f) + __logf(1.f + __expf(-fabsf(x)));
}

// ==================== warp-mma helpers (family-common PTX) ===================
__device__ __forceinline__ uint32_t smem_u32(const void* p) {
    uint32_t a;
    asm("{ .reg .u64 t; cvta.to.shared.u64 t, %1; cvt.u32.u64 %0, t; }"
        : "=r"(a) : "l"(p));
    return a;
}
__device__ __forceinline__ void ldsm4(uint32_t r[4], uint32_t a) {
    asm volatile("ldmatrix.sync.aligned.m8n8.x4.shared.b16 {%0,%1,%2,%3}, [%4];"
        : "=r"(r[0]), "=r"(r[1]), "=r"(r[2]), "=r"(r[3]) : "r"(a));
}
__device__ __forceinline__ void ldsm4t(uint32_t r[4], uint32_t a) {
    asm volatile("ldmatrix.sync.aligned.m8n8.x4.trans.shared.b16 {%0,%1,%2,%3}, [%4];"
        : "=r"(r[0]), "=r"(r[1]), "=r"(r[2]), "=r"(r[3]) : "r"(a));
}
__device__ __forceinline__ void mma_bf(float c[4], const uint32_t a[4],
                                       uint32_t b0, uint32_t b1) {
    asm volatile(
        "mma.sync.aligned.m16n8k16.row.col.f32.bf16.bf16.f32 "
        "{%0,%1,%2,%3}, {%4,%5,%6,%7}, {%8,%9}, {%0,%1,%2,%3};"
        : "+f"(c[0]), "+f"(c[1]), "+f"(c[2]), "+f"(c[3])
        : "r"(a[0]), "r"(a[1]), "r"(a[2]), "r"(a[3]), "r"(b0), "r"(b1));
}
__device__ __forceinline__ void packsplit(float x, float y, uint32_t& hi, uint32_t& lo) {
    __nv_bfloat16 hx = __float2bfloat16_rn(x), hy = __float2bfloat16_rn(y);
    __nv_bfloat162 h2; h2.x = hx; h2.y = hy;
    __nv_bfloat162 l2;
    l2.x = __float2bfloat16_rn(x - __bfloat162float(hx));
    l2.y = __float2bfloat16_rn(y - __bfloat162float(hy));
    hi = *(uint32_t*)&h2; lo = *(uint32_t*)&l2;
}
#define CP16(dst, src) asm volatile("cp.async.cg.shared.global [%0], [%1], 16;" :: "r"(dst), "l"(src))
#define CP_COMMIT() asm volatile("cp.async.commit_group;" ::: "memory")
#define CP_WAIT2()  asm volatile("cp.async.wait_group 2;" ::: "memory")

// ==================== split conversion kernels ==============================
__global__ void __launch_bounds__(256) conv_split(
    const float4* __restrict__ src, uint2* __restrict__ hi, uint2* __restrict__ lo, int n4)
{
    int i = blockIdx.x * 256 + threadIdx.x;
    if (i >= n4) return;
    float4 v = src[i];
    __nv_bfloat16 h0 = __float2bfloat16_rn(v.x), h1 = __float2bfloat16_rn(v.y);
    __nv_bfloat16 h2 = __float2bfloat16_rn(v.z), h3 = __float2bfloat16_rn(v.w);
    __nv_bfloat16 l0 = __float2bfloat16_rn(v.x - __bfloat162float(h0));
    __nv_bfloat16 l1 = __float2bfloat16_rn(v.y - __bfloat162float(h1));
    __nv_bfloat16 l2 = __float2bfloat16_rn(v.z - __bfloat162float(h2));
    __nv_bfloat16 l3 = __float2bfloat16_rn(v.w - __bfloat162float(h3));
    hi[i] = make_uint2((uint32_t)__bfloat16_as_ushort(h0) | ((uint32_t)__bfloat16_as_ushort(h1) << 16),
                       (uint32_t)__bfloat16_as_ushort(h2) | ((uint32_t)__bfloat16_as_ushort(h3) << 16));
    lo[i] = make_uint2((uint32_t)__bfloat16_as_ushort(l0) | ((uint32_t)__bfloat16_as_ushort(l1) << 16),
                       (uint32_t)__bfloat16_as_ushort(l2) | ((uint32_t)__bfloat16_as_ushort(l3) << 16));
}

// W[K][N] fp32 -> WT[N][K] bf16 hi/lo
__global__ void __launch_bounds__(256) trans_split(
    const float* __restrict__ W, __nv_bfloat16* __restrict__ th,
    __nv_bfloat16* __restrict__ tl)
{
    __shared__ float t[32][33];
    int r0 = blockIdx.y * 32, c0 = blockIdx.x * 32;
    int xx = threadIdx.x & 31, yy = threadIdx.x >> 5;
    for (int rr = yy; rr < 32; rr += 8)
        t[rr][xx] = W[(size_t)(r0 + rr) * DD + c0 + xx];
    __syncthreads();
    for (int rr = yy; rr < 32; rr += 8) {
        float v = t[xx][rr];   // = W[r0+xx][c0+rr]
        __nv_bfloat16 h = __float2bfloat16_rn(v);
        size_t o = (size_t)(c0 + rr) * DD + r0 + xx;
        th[o] = h;
        tl[o] = __float2bfloat16_rn(v - __bfloat162float(h));
    }
}

// ==================== HMMA split-bf16 GEMM: C = A @ B^T =====================
// A [M][K] bf16 hi/lo row-major, B [N][K] bf16 hi/lo. CTA 128x128, BK=64,
// 3-stage cp.async pipeline. Padded smem rows (144B) -> ldmatrix conflict-free.
#define GM_STG 73728
#define GM_SMEM (3*GM_STG)   // 221184 bytes

__global__ void __launch_bounds__(256, 1) tgemm_mma(
    const __nv_bfloat16* __restrict__ Ah, const __nv_bfloat16* __restrict__ Al,
    const __nv_bfloat16* __restrict__ Bh, const __nv_bfloat16* __restrict__ Bl,
    float* __restrict__ C)
{
    extern __shared__ char sm[];
    const uint32_t sb = smem_u32(sm);
    const int tid = threadIdx.x, wid = tid >> 5, lane = tid & 31;
    const int wm = wid >> 2, wn = wid & 3;
    const int bx = blockIdx.x, by = blockIdx.y;

    float acc[4][4][4];
#pragma unroll
    for (int i = 0; i < 4; i++)
#pragma unroll
        for (int j = 0; j < 4; j++)
#pragma unroll
            for (int r = 0; r < 4; r++) acc[i][j][r] = 0.f;

    auto load_stage = [&](int st, int kc) {
        uint32_t base = sb + st * GM_STG;
#pragma unroll
        for (int i = 0; i < 4; i++) {
            int u = tid + i * 256, row = u >> 3, c8 = u & 7;
            uint32_t off = base + row * 144 + c8 * 16;
            size_t ga = (size_t)(by * 128 + row) * DD + kc * 64 + c8 * 8;
            size_t gb = (size_t)(bx * 128 + row) * DD + kc * 64 + c8 * 8;
            CP16(off,         Ah + ga);
            CP16(off + 18432, Al + ga);
            CP16(off + 36864, Bh + gb);
            CP16(off + 55296, Bl + gb);
        }
    };
    load_stage(0, 0); CP_COMMIT();
    load_stage(1, 1); CP_COMMIT();
    load_stage(2, 2); CP_COMMIT();

    for (int kc = 0; kc < 32; kc++) {
        int st = kc % 3;
        CP_WAIT2();
        __syncthreads();
        uint32_t base = sb + st * GM_STG;
#pragma unroll
        for (int ks = 0; ks < 4; ks++) {
            uint32_t aH[4][4], aL[4][4];
#pragma unroll
            for (int mt = 0; mt < 4; mt++) {
                uint32_t aa = base + (wm * 64 + mt * 16 + (lane & 15)) * 144
                            + ks * 32 + (lane >> 4) * 16;
                ldsm4(aH[mt], aa);
                ldsm4(aL[mt], aa + 18432);
            }
#pragma unroll
            for (int nf2 = 0; nf2 < 2; nf2++) {
                uint32_t bH[4], bL[4];
                uint32_t ba = base + 36864
                            + (wn * 32 + nf2 * 16 + (lane & 7) + ((lane >> 4) << 3)) * 144
                            + ks * 32 + ((lane >> 3) & 1) * 16;
                ldsm4(bH, ba);
                ldsm4(bL, ba + 18432);
#pragma unroll
                for (int mt = 0; mt < 4; mt++) {
                    mma_bf(acc[mt][2 * nf2],     aH[mt], bH[0], bH[1]);
                    mma_bf(acc[mt][2 * nf2],     aH[mt], bL[0], bL[1]);
                    mma_bf(acc[mt][2 * nf2],     aL[mt], bH[0], bH[1]);
                    mma_bf(acc[mt][2 * nf2 + 1], aH[mt], bH[2], bH[3]);
                    mma_bf(acc[mt][2 * nf2 + 1], aH[mt], bL[2], bL[3]);
                    mma_bf(acc[mt][2 * nf2 + 1], aL[mt], bH[2], bH[3]);
                }
            }
        }
        __syncthreads();
        if (kc + 3 < 32) load_stage(st, kc + 3);
        CP_COMMIT();
    }

#pragma unroll
    for (int mt = 0; mt < 4; mt++)
#pragma unroll
        for (int nf = 0; nf < 4; nf++) {
            int row = by * 128 + wm * 64 + mt * 16 + (lane >> 2);
            int col = bx * 128 + wn * 32 + nf * 8 + (lane & 3) * 2;
            *(float2*)(C + (size_t)row * DD + col) =
                make_float2(acc[mt][nf][0], acc[mt][nf][1]);
            *(float2*)(C + (size_t)(row + 8) * DD + col) =
                make_float2(acc[mt][nf][2], acc[mt][nf][3]);
        }
}

// ---------------- clock = softplus(x @ W_clock) + 1e-6, plus its log ---------
__global__ void __launch_bounds__(128) clock_kernel(
    const float* __restrict__ x, const float* __restrict__ Wc)
{
    __shared__ float xs[DD];
    __shared__ float red[128];
    int n = blockIdx.x;
    for (int i = threadIdx.x; i < DD; i += 128) xs[i] = x[(size_t)n * DD + i];
    __syncthreads();
    int col = threadIdx.x >> 3, seg = threadIdx.x & 7;
    float s = 0.f;
    int k0 = seg * 256;
    for (int k = k0; k < k0 + 256; k++) s = fmaf(xs[k], Wc[k * HH + col], s);
    red[threadIdx.x] = s;
    __syncthreads();
    if (threadIdx.x < 16) {
        float t = 0.f;
        for (int j = 0; j < 8; j++) t += red[threadIdx.x * 8 + j];
        float ck = softplus_f(t) + 1e-6f;
        g_clockbuf[n * HH + threadIdx.x] = ck;
        g_logclock[n * HH + threadIdx.x] = __logf(ck);
    }
}

// ---------------- scan phase 1: per-chunk partials ---------------------------
__global__ void __launch_bounds__(128) scan_phase1()
{
    int c = blockIdx.x, bh = blockIdx.y, d = threadIdx.x;
    int b = bh >> 4, h = bh & 15;
    float pmax = -INFINITY, psum = 0.f, gsum = 0.f, csum = 0.f;
    for (int t = c * CL; t < (c + 1) * CL; t++) {
        int n = b * TT + t;
        float ck = g_clockbuf[n * HH + h];
        float lck = g_logclock[n * HH + h];
        size_t idx = (size_t)n * DD + h * DHD + d;
        float pv = g_p[idx] + lck;
        if (pv > pmax) { psum = psum * __expf(pmax - pv) + 1.f; pmax = pv; }
        else psum += __expf(pv - pmax);
        gsum += -softplus_fast(g_g[idx]) * ck;
        csum += ck;
    }
    int o = (bh * NC + c) * DHD + d;
    g_part_pm[o] = pmax; g_part_ps[o] = psum;
    g_part_gs[o] = gsum; g_part_cs[o] = csum;
}

// ---------------- scan phase 2: global max + exclusive chunk prefixes --------
__global__ void __launch_bounds__(128) scan_phase2()
{
    int bh = blockIdx.x, d = threadIdx.x;
    float gmax = -INFINITY;
    for (int c = 0; c < NC; c++)
        gmax = fmaxf(gmax, g_part_pm[(bh * NC + c) * DHD + d]);
    g_pmax[bh * DHD + d] = gmax;
    float ep = 0.f, eg = 0.f, ec = 0.f;
    for (int c = 0; c < NC; c++) {
        int o = (bh * NC + c) * DHD + d;
        float pm = g_part_pm[o], ps = g_part_ps[o];
        float gs = g_part_gs[o], cs = g_part_cs[o];
        g_part_ps[o] = ep; g_part_gs[o] = eg; g_part_cs[o] = ec;
        ep += ps * __expf(pm - gmax);
        eg += gs;
        ec += cs;
    }
}

// ---------------- scan phase 3: cumsums + RoPE + bf16 split q_cat/k_cat ------
__global__ void __launch_bounds__(128) scan_phase3()
{
    int c = blockIdx.x, bh = blockIdx.y, d = threadIdx.x;
    int b = bh >> 4, h = bh & 15;
    int o = (bh * NC + c) * DHD + d;
    float gmax = g_pmax[bh * DHD + d];
    float pcs = g_part_ps[o], gcs = g_part_gs[o], ccs = g_part_cs[o];
    int fi = d & 63;
    float invf = expf(-(float)fi * (logf(10000.f) / 64.f));
    float sgn = (d & 1) ? 1.f : -1.f;
    const float scale = rsqrtf(384.f);
    float cs_, sn_, cd, sd;
    sincosf((float)(c * CL) * invf, &sn_, &cs_);
    sincosf(invf, &sd, &cd);
    for (int t = c * CL; t < (c + 1) * CL; t++) {
        int n = b * TT + t;
        float ck = g_clockbuf[n * HH + h];
        float lck = g_logclock[n * HH + h];
        size_t idx = (size_t)n * DD + h * DHD + d;
        float pe = __expf(g_p[idx] + lck - gmax);
        pcs += pe;
        gcs += -softplus_fast(g_g[idx]) * ck;
        float gcp = __expf(fminf(fmaxf(gcs, -50.f), 40.f));
        ccs += ck;
        float qv = g_q[idx], kv = g_k[idx];
        float qp = __shfl_xor_sync(0xffffffffu, qv, 1);
        float kp = __shfl_xor_sync(0xffffffffu, kv, 1);
        float qr = qv * cs_ + sgn * qp * sn_;
        float kr = kv * cs_ + sgn * kp * sn_;
        size_t co = ((size_t)n * HH + h) * DC + d;
        float qs[3], kss[3];
        qs[0] = scale * qr / (pcs + 1e-8f);
        qs[1] = scale * qr * gcp;
        qs[2] = scale * qr / ccs;
        kss[0] = kr * pe;
        kss[1] = kr / (gcp + 1e-8f);
        kss[2] = kr * ck;
#pragma unroll
        for (int j = 0; j < 3; j++) {
            __nv_bfloat16 hq = __float2bfloat16_rn(qs[j]);
            g_qch[co + j * DHD] = hq;
            g_qcl[co + j * DHD] = __float2bfloat16_rn(qs[j] - __bfloat162float(hq));
            __nv_bfloat16 hk = __float2bfloat16_rn(kss[j]);
            g_kch[co + j * DHD] = hk;
            g_kcl[co + j * DHD] = __float2bfloat16_rn(kss[j] - __bfloat162float(hk));
        }
        float nc_ = cs_ * cd - sn_ * sd;
        float ns_ = sn_ * cd + cs_ * sd;
        cs_ = nc_; sn_ = ns_;
    }
}

// ==================== flash attention v3: HMMA + register softmax ============
// 8 warps x 16 q-rows = 128 queries per CTA; full 2048-key scan.
#define AT_QK 18432              // [128][72] bf16, 144B rows
#define AT_V  34816              // [128][136] bf16, 272B rows
#define AT_SMEM (4*AT_QK + 2*AT_V)   // 143360

__global__ void __launch_bounds__(256, 1) att3()
{
    extern __shared__ char sm[];
    const uint32_t sb = smem_u32(sm);
    const int tid = threadIdx.x, w = tid >> 5, lane = tid & 31;
    const int tq0 = blockIdx.x * 128;
    const int bh = blockIdx.y, b = bh >> 4, h = bh & 15;

    float acco[16][4];
    float m[2] = { -INFINITY, -INFINITY }, l[2] = { 0.f, 0.f };
#pragma unroll
    for (int i = 0; i < 16; i++)
#pragma unroll
        for (int r = 0; r < 4; r++) acco[i][r] = 0.f;

    for (int s0 = 0; s0 < TT; s0 += 128) {
        float accs[16][4];
#pragma unroll
        for (int i = 0; i < 16; i++)
#pragma unroll
            for (int r = 0; r < 4; r++) accs[i][r] = 0.f;

        // ---- scores over K-dim 384 in 6 chunks of 64 ----
        for (int kc = 0; kc < 6; kc++) {
#pragma unroll
            for (int i = 0; i < 4; i++) {
                int u = tid + i * 256, row = u >> 3, c8 = u & 7;
                int off = row * 144 + c8 * 16;
                size_t qg = ((size_t)(b * TT + tq0 + row) * HH + h) * DC + kc * 64 + c8 * 8;
                size_t kg = ((size_t)(b * TT + s0 + row) * HH + h) * DC + kc * 64 + c8 * 8;
                *(uint4*)(sm + off)             = *(const uint4*)(g_qch + qg);
                *(uint4*)(sm + AT_QK + off)     = *(const uint4*)(g_qcl + qg);
                *(uint4*)(sm + 2 * AT_QK + off) = *(const uint4*)(g_kch + kg);
                *(uint4*)(sm + 3 * AT_QK + off) = *(const uint4*)(g_kcl + kg);
            }
            __syncthreads();
#pragma unroll
            for (int ks = 0; ks < 4; ks++) {
                uint32_t aH[4], aL[4];
                uint32_t aa = sb + (w * 16 + (lane & 15)) * 144 + ks * 32 + (lane >> 4) * 16;
                ldsm4(aH, aa);
                ldsm4(aL, aa + AT_QK);
#pragma unroll
                for (int nf2 = 0; nf2 < 8; nf2++) {
                    uint32_t bH[4], bL[4];
                    uint32_t ba = sb + 2 * AT_QK
                                + (nf2 * 16 + (lane & 7) + ((lane >> 4) << 3)) * 144
                                + ks * 32 + ((lane >> 3) & 1) * 16;
                    ldsm4(bH, ba);
                    ldsm4(bL, ba + AT_QK);
                    mma_bf(accs[2 * nf2],     aH, bH[0], bH[1]);
                    mma_bf(accs[2 * nf2],     aH, bL[0], bL[1]);
                    mma_bf(accs[2 * nf2],     aL, bH[0], bH[1]);
                    mma_bf(accs[2 * nf2 + 1], aH, bH[2], bH[3]);
                    mma_bf(accs[2 * nf2 + 1], aH, bL[2], bL[3]);
                    mma_bf(accs[2 * nf2 + 1], aL, bH[2], bH[3]);
                }
            }
            __syncthreads();
        }

        // ---- online softmax in registers (rows: lane>>2 and +8) ----
#pragma unroll
        for (int hf = 0; hf < 2; hf++) {
            float mt = -INFINITY;
#pragma unroll
            for (int nf = 0; nf < 16; nf++)
                mt = fmaxf(mt, fmaxf(accs[nf][2 * hf], accs[nf][2 * hf + 1]));
            mt = fmaxf(mt, __shfl_xor_sync(0xffffffffu, mt, 1));
            mt = fmaxf(mt, __shfl_xor_sync(0xffffffffu, mt, 2));
            float mn = fmaxf(m[hf], mt);
            float corr = __expf(m[hf] - mn);
            float ls = 0.f;
#pragma unroll
            for (int nf = 0; nf < 16; nf++) {
                float p0 = __expf(accs[nf][2 * hf] - mn);
                float p1 = __expf(accs[nf][2 * hf + 1] - mn);
                accs[nf][2 * hf] = p0; accs[nf][2 * hf + 1] = p1;
                ls += p0 + p1;
            }
            ls += __shfl_xor_sync(0xffffffffu, ls, 1);
            ls += __shfl_xor_sync(0xffffffffu, ls, 2);
            l[hf] = l[hf] * corr + ls;
            m[hf] = mn;
#pragma unroll
            for (int nf = 0; nf < 16; nf++) {
                acco[nf][2 * hf]     *= corr;
                acco[nf][2 * hf + 1] *= corr;
            }
        }

        // ---- pack P into bf16 hi/lo A-fragments (registers only) ----
        uint32_t ph[8][4], pl[8][4];
#pragma unroll
        for (int kf = 0; kf < 8; kf++) {
            packsplit(accs[2 * kf][0],     accs[2 * kf][1],     ph[kf][0], pl[kf][0]);
            packsplit(accs[2 * kf][2],     accs[2 * kf][3],     ph[kf][1], pl[kf][1]);
            packsplit(accs[2 * kf + 1][0], accs[2 * kf + 1][1], ph[kf][2], pl[kf][2]);
            packsplit(accs[2 * kf + 1][2], accs[2 * kf + 1][3], ph[kf][3], pl[kf][3]);
        }

        // ---- load V tile (bf16 hi/lo) ----
#pragma unroll
        for (int i = 0; i < 8; i++) {
            int u = tid + i * 256, row = u >> 4, c16 = u & 15;
            int off = row * 272 + c16 * 16;
            size_t vg = (size_t)(b * TT + s0 + row) * DD + h * 128 + c16 * 8;
            *(uint4*)(sm + 4 * AT_QK + off)        = *(const uint4*)(g_vh + vg);
            *(uint4*)(sm + 4 * AT_QK + AT_V + off) = *(const uint4*)(g_vl + vg);
        }
        __syncthreads();

        // ---- PV: O += P @ V ----
#pragma unroll
        for (int nf2 = 0; nf2 < 8; nf2++) {
#pragma unroll
            for (int kf = 0; kf < 8; kf++) {
                uint32_t vH[4], vL[4];
                uint32_t va = sb + 4 * AT_QK
                            + (kf * 16 + (lane & 7) + (((lane >> 3) & 1) << 3)) * 272
                            + (nf2 * 16 + ((lane >> 4) << 3)) * 2;
                ldsm4t(vH, va);
                ldsm4t(vL, va + AT_V);
                mma_bf(acco[2 * nf2],     ph[kf], vH[0], vH[1]);
                mma_bf(acco[2 * nf2],     ph[kf], vL[0], vL[1]);
                mma_bf(acco[2 * nf2],     pl[kf], vH[0], vH[1]);
                mma_bf(acco[2 * nf2 + 1], ph[kf], vH[2], vH[3]);
                mma_bf(acco[2 * nf2 + 1], ph[kf], vL[2], vL[3]);
                mma_bf(acco[2 * nf2 + 1], pl[kf], vH[2], vH[3]);
            }
        }
        __syncthreads();
    }

    // ---- epilogue: write O as bf16 hi/lo (feeds final GEMM directly) ----
    float i0 = 1.f / l[0], i1 = 1.f / l[1];
    int r0 = b * TT + tq0 + w * 16 + (lane >> 2);
#pragma unroll
    for (int nf = 0; nf < 16; nf++) {
        int col = h * 128 + nf * 8 + 2 * (lane & 3);
        size_t o0 = (size_t)r0 * DD + col;
        size_t o1 = o0 + (size_t)8 * DD;
        uint32_t hi, lo;
        packsplit(acco[nf][0] * i0, acco[nf][1] * i0, hi, lo);
        *(uint32_t*)(g_ah + o0) = hi; *(uint32_t*)(g_al + o0) = lo;
        packsplit(acco[nf][2] * i1, acco[nf][3] * i1, hi, lo);
        *(uint32_t*)(g_ah + o1) = hi; *(uint32_t*)(g_al + o1) = lo;
    }
}

// ---------------- launch ----------------------------------------------------
extern "C" void kernel_launch(void* const* d_in, const int* in_sizes, int n_in,
                              void* d_out, int out_size)
{
    const float* x   = (const float*)d_in[0];
    const float* Wq  = (const float*)d_in[1];
    const float* Wk  = (const float*)d_in[2];
    const float* Wv  = (const float*)d_in[3];
    const float* Wg  = (const float*)d_in[4];
    const float* Wp  = (const float*)d_in[5];
    const float* Wcl = (const float*)d_in[6];
    const float* Wc  = (const float*)d_in[7];
    float* out = (float*)d_out;

    float *pq, *pk, *pv, *pp, *pg;
    __nv_bfloat16 *pxh, *pxl, *pah, *pal, *pvh, *pvl, *pwth, *pwtl;
    cudaGetSymbolAddress((void**)&pq,  g_q);
    cudaGetSymbolAddress((void**)&pk,  g_k);
    cudaGetSymbolAddress((void**)&pv,  g_v);
    cudaGetSymbolAddress((void**)&pp,  g_p);
    cudaGetSymbolAddress((void**)&pg,  g_g);
    cudaGetSymbolAddress((void**)&pxh, g_xh);
    cudaGetSymbolAddress((void**)&pxl, g_xl);
    cudaGetSymbolAddress((void**)&pah, g_ah);
    cudaGetSymbolAddress((void**)&pal, g_al);
    cudaGetSymbolAddress((void**)&pvh, g_vh);
    cudaGetSymbolAddress((void**)&pvl, g_vl);
    cudaGetSymbolAddress((void**)&pwth, g_wth);
    cudaGetSymbolAddress((void**)&pwtl, g_wtl);

    cudaFuncSetAttribute(tgemm_mma, cudaFuncAttributeMaxDynamicSharedMemorySize, GM_SMEM);
    cudaFuncSetAttribute(att3, cudaFuncAttributeMaxDynamicSharedMemorySize, AT_SMEM);

    const size_t WSZ = (size_t)DD * DD;
    conv_split<<<(NROWS * DD / 4 + 255) / 256, 256>>>(
        (const float4*)x, (uint2*)pxh, (uint2*)pxl, NROWS * DD / 4);
    dim3 wgrid(DD / 32, DD / 32);
    trans_split<<<wgrid, 256>>>(Wq, pwth + 0 * WSZ, pwtl + 0 * WSZ);
    trans_split<<<wgrid, 256>>>(Wk, pwth + 1 * WSZ, pwtl + 1 * WSZ);
    trans_split<<<wgrid, 256>>>(Wv, pwth + 2 * WSZ, pwtl + 2 * WSZ);
    trans_split<<<wgrid, 256>>>(Wp, pwth + 3 * WSZ, pwtl + 3 * WSZ);
    trans_split<<<wgrid, 256>>>(Wg, pwth + 4 * WSZ, pwtl + 4 * WSZ);
    trans_split<<<wgrid, 256>>>(Wc, pwth + 5 * WSZ, pwtl + 5 * WSZ);
    clock_kernel<<<NROWS, 128>>>(x, Wcl);

    dim3 ggrid(DD / 128, NROWS / 128);  // (16, 32)
    tgemm_mma<<<ggrid, 256, GM_SMEM>>>(pxh, pxl, pwth + 0 * WSZ, pwtl + 0 * WSZ, pq);
    tgemm_mma<<<ggrid, 256, GM_SMEM>>>(pxh, pxl, pwth + 1 * WSZ, pwtl + 1 * WSZ, pk);
    tgemm_mma<<<ggrid, 256, GM_SMEM>>>(pxh, pxl, pwth + 2 * WSZ, pwtl + 2 * WSZ, pv);
    tgemm_mma<<<ggrid, 256, GM_SMEM>>>(pxh, pxl, pwth + 3 * WSZ, pwtl + 3 * WSZ, pp);
    tgemm_mma<<<ggrid, 256, GM_SMEM>>>(pxh, pxl, pwth + 4 * WSZ, pwtl + 4 * WSZ, pg);

    conv_split<<<(NROWS * DD / 4 + 255) / 256, 256>>>(
        (const float4*)pv, (uint2*)pvh, (uint2*)pvl, NROWS * DD / 4);

    scan_phase1<<<dim3(NC, BB * HH), 128>>>();
    scan_phase2<<<BB * HH, 128>>>();
    scan_phase3<<<dim3(NC, BB * HH), 128>>>();

    att3<<<dim3(TT / 128, BB * HH), 256, AT_SMEM>>>();

    tgemm_mma<<<ggrid, 256, GM_SMEM>>>(pah, pal, pwth + 5 * WSZ, pwtl + 5 * WSZ, out);
}

// round 7
// speedup vs baseline: 5.4792x; 1.1198x over previous
#include <cuda_runtime.h>
#include <cuda_bf16.h>
#include <math.h>
#include <stdint.h>

#define BB 2
#define TT 2048
#define DD 2048
#define HH 16
#define DHD 128
#define DC 384
#define NROWS (BB*TT)        // 4096
#define NC 32
#define CL (TT/NC)           // 64

// ---------------- scratch (device globals: no runtime allocation allowed) ----
__device__ float g_q[NROWS*DD];
__device__ float g_k[NROWS*DD];
__device__ float g_p[NROWS*DD];
__device__ float g_g[NROWS*DD];
__device__ float g_clockbuf[NROWS*HH];
__device__ float g_logclock[NROWS*HH];
__device__ float g_pmax[BB*HH*DHD];
__device__ float g_part_pm[BB*HH*NC*DHD];
__device__ float g_part_ps[BB*HH*NC*DHD];
__device__ float g_part_gs[BB*HH*NC*DHD];
__device__ float g_part_cs[BB*HH*NC*DHD];

// bf16 split operands
__device__ __align__(16) __nv_bfloat16 g_xh[(size_t)NROWS*DD];
__device__ __align__(16) __nv_bfloat16 g_xl[(size_t)NROWS*DD];
__device__ __align__(16) __nv_bfloat16 g_ah[(size_t)NROWS*DD];   // attention out hi
__device__ __align__(16) __nv_bfloat16 g_al[(size_t)NROWS*DD];   // attention out lo
__device__ __align__(16) __nv_bfloat16 g_vh[(size_t)NROWS*DD];
__device__ __align__(16) __nv_bfloat16 g_vl[(size_t)NROWS*DD];
__device__ __align__(16) __nv_bfloat16 g_wth[(size_t)6*DD*DD];   // W^T hi [N][K]
__device__ __align__(16) __nv_bfloat16 g_wtl[(size_t)6*DD*DD];   // W^T lo
__device__ __align__(16) __nv_bfloat16 g_qch[(size_t)NROWS*HH*DC];
__device__ __align__(16) __nv_bfloat16 g_qcl[(size_t)NROWS*HH*DC];
__device__ __align__(16) __nv_bfloat16 g_kch[(size_t)NROWS*HH*DC];
__device__ __align__(16) __nv_bfloat16 g_kcl[(size_t)NROWS*HH*DC];

__device__ __forceinline__ float softplus_f(float x) {
    return fmaxf(x, 0.f) + log1pf(expf(-fabsf(x)));
}
__device__ __forceinline__ float softplus_fast(float x) {
    return fmaxf(x, 0.f) + __logf(1.f + __expf(-fabsf(x)));
}

// ==================== warp-mma helpers (family-common PTX) ===================
__device__ __forceinline__ uint32_t smem_u32(const void* p) {
    uint32_t a;
    asm("{ .reg .u64 t; cvta.to.shared.u64 t, %1; cvt.u32.u64 %0, t; }"
        : "=r"(a) : "l"(p));
    return a;
}
__device__ __forceinline__ void ldsm4(uint32_t r[4], uint32_t a) {
    asm volatile("ldmatrix.sync.aligned.m8n8.x4.shared.b16 {%0,%1,%2,%3}, [%4];"
        : "=r"(r[0]), "=r"(r[1]), "=r"(r[2]), "=r"(r[3]) : "r"(a));
}
__device__ __forceinline__ void ldsm4t(uint32_t r[4], uint32_t a) {
    asm volatile("ldmatrix.sync.aligned.m8n8.x4.trans.shared.b16 {%0,%1,%2,%3}, [%4];"
        : "=r"(r[0]), "=r"(r[1]), "=r"(r[2]), "=r"(r[3]) : "r"(a));
}
__device__ __forceinline__ void mma_bf(float c[4], const uint32_t a[4],
                                       uint32_t b0, uint32_t b1) {
    asm volatile(
        "mma.sync.aligned.m16n8k16.row.col.f32.bf16.bf16.f32 "
        "{%0,%1,%2,%3}, {%4,%5,%6,%7}, {%8,%9}, {%0,%1,%2,%3};"
        : "+f"(c[0]), "+f"(c[1]), "+f"(c[2]), "+f"(c[3])
        : "r"(a[0]), "r"(a[1]), "r"(a[2]), "r"(a[3]), "r"(b0), "r"(b1));
}
__device__ __forceinline__ void packsplit(float x, float y, uint32_t& hi, uint32_t& lo) {
    __nv_bfloat16 hx = __float2bfloat16_rn(x), hy = __float2bfloat16_rn(y);
    __nv_bfloat162 h2; h2.x = hx; h2.y = hy;
    __nv_bfloat162 l2;
    l2.x = __float2bfloat16_rn(x - __bfloat162float(hx));
    l2.y = __float2bfloat16_rn(y - __bfloat162float(hy));
    hi = *(uint32_t*)&h2; lo = *(uint32_t*)&l2;
}
#define CP16(dst, src) asm volatile("cp.async.cg.shared.global [%0], [%1], 16;" :: "r"(dst), "l"(src))
#define CP_COMMIT() asm volatile("cp.async.commit_group;" ::: "memory")
#define CP_WAIT0()  asm volatile("cp.async.wait_group 0;" ::: "memory")
#define CP_WAIT1()  asm volatile("cp.async.wait_group 1;" ::: "memory")

// ==================== split conversion kernels ==============================
__global__ void __launch_bounds__(256) conv_split(
    const float4* __restrict__ src, uint2* __restrict__ hi, uint2* __restrict__ lo, int n4)
{
    int i = blockIdx.x * 256 + threadIdx.x;
    if (i >= n4) return;
    float4 v = src[i];
    __nv_bfloat16 h0 = __float2bfloat16_rn(v.x), h1 = __float2bfloat16_rn(v.y);
    __nv_bfloat16 h2 = __float2bfloat16_rn(v.z), h3 = __float2bfloat16_rn(v.w);
    __nv_bfloat16 l0 = __float2bfloat16_rn(v.x - __bfloat162float(h0));
    __nv_bfloat16 l1 = __float2bfloat16_rn(v.y - __bfloat162float(h1));
    __nv_bfloat16 l2 = __float2bfloat16_rn(v.z - __bfloat162float(h2));
    __nv_bfloat16 l3 = __float2bfloat16_rn(v.w - __bfloat162float(h3));
    hi[i] = make_uint2((uint32_t)__bfloat16_as_ushort(h0) | ((uint32_t)__bfloat16_as_ushort(h1) << 16),
                       (uint32_t)__bfloat16_as_ushort(h2) | ((uint32_t)__bfloat16_as_ushort(h3) << 16));
    lo[i] = make_uint2((uint32_t)__bfloat16_as_ushort(l0) | ((uint32_t)__bfloat16_as_ushort(l1) << 16),
                       (uint32_t)__bfloat16_as_ushort(l2) | ((uint32_t)__bfloat16_as_ushort(l3) << 16));
}

// W[K][N] fp32 -> WT[N][K] bf16 hi/lo
__global__ void __launch_bounds__(256) trans_split(
    const float* __restrict__ W, __nv_bfloat16* __restrict__ th,
    __nv_bfloat16* __restrict__ tl)
{
    __shared__ float t[32][33];
    int r0 = blockIdx.y * 32, c0 = blockIdx.x * 32;
    int xx = threadIdx.x & 31, yy = threadIdx.x >> 5;
    for (int rr = yy; rr < 32; rr += 8)
        t[rr][xx] = W[(size_t)(r0 + rr) * DD + c0 + xx];
    __syncthreads();
    for (int rr = yy; rr < 32; rr += 8) {
        float v = t[xx][rr];   // = W[r0+xx][c0+rr]
        __nv_bfloat16 h = __float2bfloat16_rn(v);
        size_t o = (size_t)(c0 + rr) * DD + r0 + xx;
        th[o] = h;
        tl[o] = __float2bfloat16_rn(v - __bfloat162float(h));
    }
}

// ==================== HMMA split-bf16 GEMM: C = A @ B^T =====================
// A [M][K] bf16 hi/lo row-major, B [N][K] bf16 hi/lo. CTA 128x128, BK=64,
// 3-buffer cp.async pipeline, 1 sync/chunk. Padded rows (144B).
// fused != 0: projection mode — bx in [0,80), B rows span 5 weights; epilogue
// dispatches output buffer by bx>>4 (j==2 writes bf16 split V directly).
#define GM_STG 73728
#define GM_SMEM (3*GM_STG)   // 221184 bytes

__global__ void __launch_bounds__(256, 1) tgemm_mma(
    const __nv_bfloat16* __restrict__ Ah, const __nv_bfloat16* __restrict__ Al,
    const __nv_bfloat16* __restrict__ Bh, const __nv_bfloat16* __restrict__ Bl,
    float* __restrict__ C, int fused)
{
    extern __shared__ char sm[];
    const uint32_t sb = smem_u32(sm);
    const int tid = threadIdx.x, wid = tid >> 5, lane = tid & 31;
    const int wm = wid >> 2, wn = wid & 3;
    const int bx = blockIdx.x, by = blockIdx.y;

    float acc[4][4][4];
#pragma unroll
    for (int i = 0; i < 4; i++)
#pragma unroll
        for (int j = 0; j < 4; j++)
#pragma unroll
            for (int r = 0; r < 4; r++) acc[i][j][r] = 0.f;

    auto load_stage = [&](int st, int kc) {
        uint32_t base = sb + st * GM_STG;
#pragma unroll
        for (int i = 0; i < 4; i++) {
            int u = tid + i * 256, row = u >> 3, c8 = u & 7;
            uint32_t off = base + row * 144 + c8 * 16;
            size_t ga = (size_t)(by * 128 + row) * DD + kc * 64 + c8 * 8;
            size_t gb = (size_t)(bx * 128 + row) * DD + kc * 64 + c8 * 8;
            CP16(off,         Ah + ga);
            CP16(off + 18432, Al + ga);
            CP16(off + 36864, Bh + gb);
            CP16(off + 55296, Bl + gb);
        }
    };
    load_stage(0, 0); CP_COMMIT();
    load_stage(1, 1); CP_COMMIT();

    for (int kc = 0; kc < 32; kc++) {
        int st = kc % 3;
        if (kc < 31) { CP_WAIT1(); } else { CP_WAIT0(); }
        __syncthreads();
        if (kc + 2 < 32) { load_stage((kc + 2) % 3, kc + 2); CP_COMMIT(); }
        uint32_t base = sb + st * GM_STG;
#pragma unroll
        for (int ks = 0; ks < 4; ks++) {
            uint32_t aH[4][4], aL[4][4];
#pragma unroll
            for (int mt = 0; mt < 4; mt++) {
                uint32_t aa = base + (wm * 64 + mt * 16 + (lane & 15)) * 144
                            + ks * 32 + (lane >> 4) * 16;
                ldsm4(aH[mt], aa);
                ldsm4(aL[mt], aa + 18432);
            }
#pragma unroll
            for (int nf2 = 0; nf2 < 2; nf2++) {
                uint32_t bH[4], bL[4];
                uint32_t ba = base + 36864
                            + (wn * 32 + nf2 * 16 + (lane & 7) + ((lane >> 4) << 3)) * 144
                            + ks * 32 + ((lane >> 3) & 1) * 16;
                ldsm4(bH, ba);
                ldsm4(bL, ba + 18432);
#pragma unroll
                for (int mt = 0; mt < 4; mt++) {
                    mma_bf(acc[mt][2 * nf2],     aH[mt], bH[0], bH[1]);
                    mma_bf(acc[mt][2 * nf2],     aH[mt], bL[0], bL[1]);
                    mma_bf(acc[mt][2 * nf2],     aL[mt], bH[0], bH[1]);
                    mma_bf(acc[mt][2 * nf2 + 1], aH[mt], bH[2], bH[3]);
                    mma_bf(acc[mt][2 * nf2 + 1], aH[mt], bL[2], bL[3]);
                    mma_bf(acc[mt][2 * nf2 + 1], aL[mt], bH[2], bH[3]);
                }
            }
        }
    }

    if (!fused) {
#pragma unroll
        for (int mt = 0; mt < 4; mt++)
#pragma unroll
            for (int nf = 0; nf < 4; nf++) {
                int row = by * 128 + wm * 64 + mt * 16 + (lane >> 2);
                int col = bx * 128 + wn * 32 + nf * 8 + (lane & 3) * 2;
                *(float2*)(C + (size_t)row * DD + col) =
                    make_float2(acc[mt][nf][0], acc[mt][nf][1]);
                *(float2*)(C + (size_t)(row + 8) * DD + col) =
                    make_float2(acc[mt][nf][2], acc[mt][nf][3]);
            }
    } else {
        int j = bx >> 4;
        int colb = (bx & 15) * 128;
        if (j == 2) {
#pragma unroll
            for (int mt = 0; mt < 4; mt++)
#pragma unroll
                for (int nf = 0; nf < 4; nf++) {
                    int row = by * 128 + wm * 64 + mt * 16 + (lane >> 2);
                    int col = colb + wn * 32 + nf * 8 + (lane & 3) * 2;
                    uint32_t hi, lo;
                    packsplit(acc[mt][nf][0], acc[mt][nf][1], hi, lo);
                    *(uint32_t*)(g_vh + (size_t)row * DD + col) = hi;
                    *(uint32_t*)(g_vl + (size_t)row * DD + col) = lo;
                    packsplit(acc[mt][nf][2], acc[mt][nf][3], hi, lo);
                    *(uint32_t*)(g_vh + (size_t)(row + 8) * DD + col) = hi;
                    *(uint32_t*)(g_vl + (size_t)(row + 8) * DD + col) = lo;
                }
        } else {
            float* Cj = (j == 0) ? g_q : (j == 1) ? g_k : (j == 3) ? g_p : g_g;
#pragma unroll
            for (int mt = 0; mt < 4; mt++)
#pragma unroll
                for (int nf = 0; nf < 4; nf++) {
                    int row = by * 128 + wm * 64 + mt * 16 + (lane >> 2);
                    int col = colb + wn * 32 + nf * 8 + (lane & 3) * 2;
                    *(float2*)(Cj + (size_t)row * DD + col) =
                        make_float2(acc[mt][nf][0], acc[mt][nf][1]);
                    *(float2*)(Cj + (size_t)(row + 8) * DD + col) =
                        make_float2(acc[mt][nf][2], acc[mt][nf][3]);
                }
        }
    }
}

// ---------------- clock = softplus(x @ W_clock) + 1e-6, plus its log ---------
__global__ void __launch_bounds__(128) clock_kernel(
    const float* __restrict__ x, const float* __restrict__ Wc)
{
    __shared__ float xs[DD];
    __shared__ float red[128];
    int n = blockIdx.x;
    for (int i = threadIdx.x; i < DD; i += 128) xs[i] = x[(size_t)n * DD + i];
    __syncthreads();
    int col = threadIdx.x >> 3, seg = threadIdx.x & 7;
    float s = 0.f;
    int k0 = seg * 256;
    for (int k = k0; k < k0 + 256; k++) s = fmaf(xs[k], Wc[k * HH + col], s);
    red[threadIdx.x] = s;
    __syncthreads();
    if (threadIdx.x < 16) {
        float t = 0.f;
        for (int j = 0; j < 8; j++) t += red[threadIdx.x * 8 + j];
        float ck = softplus_f(t) + 1e-6f;
        g_clockbuf[n * HH + threadIdx.x] = ck;
        g_logclock[n * HH + threadIdx.x] = __logf(ck);
    }
}

// ---------------- scan phase 1: per-chunk partials ---------------------------
__global__ void __launch_bounds__(128) scan_phase1()
{
    int c = blockIdx.x, bh = blockIdx.y, d = threadIdx.x;
    int b = bh >> 4, h = bh & 15;
    float pmax = -INFINITY, psum = 0.f, gsum = 0.f, csum = 0.f;
    for (int t = c * CL; t < (c + 1) * CL; t++) {
        int n = b * TT + t;
        float ck = g_clockbuf[n * HH + h];
        float lck = g_logclock[n * HH + h];
        size_t idx = (size_t)n * DD + h * DHD + d;
        float pv = g_p[idx] + lck;
        if (pv > pmax) { psum = psum * __expf(pmax - pv) + 1.f; pmax = pv; }
        else psum += __expf(pv - pmax);
        gsum += -softplus_fast(g_g[idx]) * ck;
        csum += ck;
    }
    int o = (bh * NC + c) * DHD + d;
    g_part_pm[o] = pmax; g_part_ps[o] = psum;
    g_part_gs[o] = gsum; g_part_cs[o] = csum;
}

// ---------------- scan phase 2: global max + exclusive chunk prefixes --------
__global__ void __launch_bounds__(128) scan_phase2()
{
    int bh = blockIdx.x, d = threadIdx.x;
    float gmax = -INFINITY;
    for (int c = 0; c < NC; c++)
        gmax = fmaxf(gmax, g_part_pm[(bh * NC + c) * DHD + d]);
    g_pmax[bh * DHD + d] = gmax;
    float ep = 0.f, eg = 0.f, ec = 0.f;
    for (int c = 0; c < NC; c++) {
        int o = (bh * NC + c) * DHD + d;
        float pm = g_part_pm[o], ps = g_part_ps[o];
        float gs = g_part_gs[o], cs = g_part_cs[o];
        g_part_ps[o] = ep; g_part_gs[o] = eg; g_part_cs[o] = ec;
        ep += ps * __expf(pm - gmax);
        eg += gs;
        ec += cs;
    }
}

// ---------------- scan phase 3: cumsums + RoPE + bf16 split q_cat/k_cat ------
__global__ void __launch_bounds__(128) scan_phase3()
{
    int c = blockIdx.x, bh = blockIdx.y, d = threadIdx.x;
    int b = bh >> 4, h = bh & 15;
    int o = (bh * NC + c) * DHD + d;
    float gmax = g_pmax[bh * DHD + d];
    float pcs = g_part_ps[o], gcs = g_part_gs[o], ccs = g_part_cs[o];
    int fi = d & 63;
    float invf = expf(-(float)fi * (logf(10000.f) / 64.f));
    float sgn = (d & 1) ? 1.f : -1.f;
    const float scale = rsqrtf(384.f);
    float cs_, sn_, cd, sd;
    sincosf((float)(c * CL) * invf, &sn_, &cs_);
    sincosf(invf, &sd, &cd);
    for (int t = c * CL; t < (c + 1) * CL; t++) {
        int n = b * TT + t;
        float ck = g_clockbuf[n * HH + h];
        float lck = g_logclock[n * HH + h];
        size_t idx = (size_t)n * DD + h * DHD + d;
        float pe = __expf(g_p[idx] + lck - gmax);
        pcs += pe;
        gcs += -softplus_fast(g_g[idx]) * ck;
        float gcp = __expf(fminf(fmaxf(gcs, -50.f), 40.f));
        ccs += ck;
        float qv = g_q[idx], kv = g_k[idx];
        float qp = __shfl_xor_sync(0xffffffffu, qv, 1);
        float kp = __shfl_xor_sync(0xffffffffu, kv, 1);
        float qr = qv * cs_ + sgn * qp * sn_;
        float kr = kv * cs_ + sgn * kp * sn_;
        size_t co = ((size_t)n * HH + h) * DC + d;
        float qs[3], kss[3];
        qs[0] = scale * qr / (pcs + 1e-8f);
        qs[1] = scale * qr * gcp;
        qs[2] = scale * qr / ccs;
        kss[0] = kr * pe;
        kss[1] = kr / (gcp + 1e-8f);
        kss[2] = kr * ck;
#pragma unroll
        for (int j = 0; j < 3; j++) {
            __nv_bfloat16 hq = __float2bfloat16_rn(qs[j]);
            g_qch[co + j * DHD] = hq;
            g_qcl[co + j * DHD] = __float2bfloat16_rn(qs[j] - __bfloat162float(hq));
            __nv_bfloat16 hk = __float2bfloat16_rn(kss[j]);
            g_kch[co + j * DHD] = hk;
            g_kcl[co + j * DHD] = __float2bfloat16_rn(kss[j] - __bfloat162float(hk));
        }
        float nc_ = cs_ * cd - sn_ * sd;
        float ns_ = sn_ * cd + cs_ * sd;
        cs_ = nc_; sn_ = ns_;
    }
}

// ==================== flash attention v4: HMMA + cp.async pipeline ===========
// 8 warps x 16 q-rows = 128 queries per CTA; full 2048-key scan.
// QK double-buffered chunk pipeline; V loaded async at iteration start.
#define AT_STG 73728             // qh/ql/kh/kl, [128][72] bf16, 144B rows
#define AT_VOFF (2*AT_STG)       // 147456
#define AT_V 34816               // [128][136] bf16, 272B rows
#define AT_SMEM (2*AT_STG + 2*AT_V)   // 217088

__global__ void __launch_bounds__(256, 1) att3()
{
    extern __shared__ char sm[];
    const uint32_t sb = smem_u32(sm);
    const int tid = threadIdx.x, w = tid >> 5, lane = tid & 31;
    const int tq0 = blockIdx.x * 128;
    const int bh = blockIdx.y, b = bh >> 4, h = bh & 15;

    float acco[16][4];
    float m[2] = { -INFINITY, -INFINITY }, l[2] = { 0.f, 0.f };
#pragma unroll
    for (int i = 0; i < 16; i++)
#pragma unroll
        for (int r = 0; r < 4; r++) acco[i][r] = 0.f;

    auto issue_qk = [&](int buf, int s0, int kc) {
        uint32_t base = sb + buf * AT_STG;
#pragma unroll
        for (int i = 0; i < 4; i++) {
            int u = tid + i * 256, row = u >> 3, c8 = u & 7;
            uint32_t off = base + row * 144 + c8 * 16;
            size_t qg = ((size_t)(b * TT + tq0 + row) * HH + h) * DC + kc * 64 + c8 * 8;
            size_t kg = ((size_t)(b * TT + s0 + row) * HH + h) * DC + kc * 64 + c8 * 8;
            CP16(off,         g_qch + qg);
            CP16(off + 18432, g_qcl + qg);
            CP16(off + 36864, g_kch + kg);
            CP16(off + 55296, g_kcl + kg);
        }
    };

    for (int s0 = 0; s0 < TT; s0 += 128) {
        // issue V (whole tile) + QK chunk 0 -> group G0; QK chunk 1 -> G1
#pragma unroll
        for (int i = 0; i < 8; i++) {
            int u = tid + i * 256, row = u >> 4, c16 = u & 15;
            uint32_t off = sb + AT_VOFF + row * 272 + c16 * 16;
            size_t vg = (size_t)(b * TT + s0 + row) * DD + h * 128 + c16 * 8;
            CP16(off,        g_vh + vg);
            CP16(off + AT_V, g_vl + vg);
        }
        issue_qk(0, s0, 0); CP_COMMIT();
        issue_qk(1, s0, 1); CP_COMMIT();

        float accs[16][4];
#pragma unroll
        for (int i = 0; i < 16; i++)
#pragma unroll
            for (int r = 0; r < 4; r++) accs[i][r] = 0.f;

        // ---- scores over K-dim 384 in 6 chunks of 64 ----
        for (int kc = 0; kc < 6; kc++) {
            if (kc < 5) { CP_WAIT1(); } else { CP_WAIT0(); }
            __syncthreads();
            uint32_t base = sb + (kc & 1) * AT_STG;
#pragma unroll
            for (int ks = 0; ks < 4; ks++) {
                uint32_t aH[4], aL[4];
                uint32_t aa = base + (w * 16 + (lane & 15)) * 144 + ks * 32 + (lane >> 4) * 16;
                ldsm4(aH, aa);
                ldsm4(aL, aa + 18432);
#pragma unroll
                for (int nf2 = 0; nf2 < 8; nf2++) {
                    uint32_t bH[4], bL[4];
                    uint32_t ba = base + 36864
                                + (nf2 * 16 + (lane & 7) + ((lane >> 4) << 3)) * 144
                                + ks * 32 + ((lane >> 3) & 1) * 16;
                    ldsm4(bH, ba);
                    ldsm4(bL, ba + 18432);
                    mma_bf(accs[2 * nf2],     aH, bH[0], bH[1]);
                    mma_bf(accs[2 * nf2],     aH, bL[0], bL[1]);
                    mma_bf(accs[2 * nf2],     aL, bH[0], bH[1]);
                    mma_bf(accs[2 * nf2 + 1], aH, bH[2], bH[3]);
                    mma_bf(accs[2 * nf2 + 1], aH, bL[2], bL[3]);
                    mma_bf(accs[2 * nf2 + 1], aL, bH[2], bH[3]);
                }
            }
            __syncthreads();
            if (kc + 2 < 6) { issue_qk(kc & 1, s0, kc + 2); CP_COMMIT(); }
        }

        // ---- online softmax in registers (rows: lane>>2 and +8) ----
#pragma unroll
        for (int hf = 0; hf < 2; hf++) {
            float mt = -INFINITY;
#pragma unroll
            for (int nf = 0; nf < 16; nf++)
                mt = fmaxf(mt, fmaxf(accs[nf][2 * hf], accs[nf][2 * hf + 1]));
            mt = fmaxf(mt, __shfl_xor_sync(0xffffffffu, mt, 1));
            mt = fmaxf(mt, __shfl_xor_sync(0xffffffffu, mt, 2));
            float mn = fmaxf(m[hf], mt);
            float corr = __expf(m[hf] - mn);
            float ls = 0.f;
#pragma unroll
            for (int nf = 0; nf < 16; nf++) {
                float p0 = __expf(accs[nf][2 * hf] - mn);
                float p1 = __expf(accs[nf][2 * hf + 1] - mn);
                accs[nf][2 * hf] = p0; accs[nf][2 * hf + 1] = p1;
                ls += p0 + p1;
            }
            ls += __shfl_xor_sync(0xffffffffu, ls, 1);
            ls += __shfl_xor_sync(0xffffffffu, ls, 2);
            l[hf] = l[hf] * corr + ls;
            m[hf] = mn;
#pragma unroll
            for (int nf = 0; nf < 16; nf++) {
                acco[nf][2 * hf]     *= corr;
                acco[nf][2 * hf + 1] *= corr;
            }
        }

        // ---- pack P into bf16 hi/lo A-fragments (registers only) ----
        uint32_t ph[8][4], pl[8][4];
#pragma unroll
        for (int kf = 0; kf < 8; kf++) {
            packsplit(accs[2 * kf][0],     accs[2 * kf][1],     ph[kf][0], pl[kf][0]);
            packsplit(accs[2 * kf][2],     accs[2 * kf][3],     ph[kf][1], pl[kf][1]);
            packsplit(accs[2 * kf + 1][0], accs[2 * kf + 1][1], ph[kf][2], pl[kf][2]);
            packsplit(accs[2 * kf + 1][2], accs[2 * kf + 1][3], ph[kf][3], pl[kf][3]);
        }

        // ---- PV: O += P @ V  (V landed with group G0) ----
#pragma unroll
        for (int nf2 = 0; nf2 < 8; nf2++) {
#pragma unroll
            for (int kf = 0; kf < 8; kf++) {
                uint32_t vH[4], vL[4];
                uint32_t va = sb + AT_VOFF
                            + (kf * 16 + (lane & 7) + (((lane >> 3) & 1) << 3)) * 272
                            + (nf2 * 16 + ((lane >> 4) << 3)) * 2;
                ldsm4t(vH, va);
                ldsm4t(vL, va + AT_V);
                mma_bf(acco[2 * nf2],     ph[kf], vH[0], vH[1]);
                mma_bf(acco[2 * nf2],     ph[kf], vL[0], vL[1]);
                mma_bf(acco[2 * nf2],     pl[kf], vH[0], vH[1]);
                mma_bf(acco[2 * nf2 + 1], ph[kf], vH[2], vH[3]);
                mma_bf(acco[2 * nf2 + 1], ph[kf], vL[2], vL[3]);
                mma_bf(acco[2 * nf2 + 1], pl[kf], vH[2], vH[3]);
            }
        }
        __syncthreads();
    }

    // ---- epilogue: write O as bf16 hi/lo (feeds final GEMM directly) ----
    float i0 = 1.f / l[0], i1 = 1.f / l[1];
    int r0 = b * TT + tq0 + w * 16 + (lane >> 2);
#pragma unroll
    for (int nf = 0; nf < 16; nf++) {
        int col = h * 128 + nf * 8 + 2 * (lane & 3);
        size_t o0 = (size_t)r0 * DD + col;
        size_t o1 = o0 + (size_t)8 * DD;
        uint32_t hi, lo;
        packsplit(acco[nf][0] * i0, acco[nf][1] * i0, hi, lo);
        *(uint32_t*)(g_ah + o0) = hi; *(uint32_t*)(g_al + o0) = lo;
        packsplit(acco[nf][2] * i1, acco[nf][3] * i1, hi, lo);
        *(uint32_t*)(g_ah + o1) = hi; *(uint32_t*)(g_al + o1) = lo;
    }
}

// ---------------- launch ----------------------------------------------------
extern "C" void kernel_launch(void* const* d_in, const int* in_sizes, int n_in,
                              void* d_out, int out_size)
{
    const float* x   = (const float*)d_in[0];
    const float* Wq  = (const float*)d_in[1];
    const float* Wk  = (const float*)d_in[2];
    const float* Wv  = (const float*)d_in[3];
    const float* Wg  = (const float*)d_in[4];
    const float* Wp  = (const float*)d_in[5];
    const float* Wcl = (const float*)d_in[6];
    const float* Wc  = (const float*)d_in[7];
    float* out = (float*)d_out;

    __nv_bfloat16 *pxh, *pxl, *pah, *pal, *pwth, *pwtl;
    cudaGetSymbolAddress((void**)&pxh, g_xh);
    cudaGetSymbolAddress((void**)&pxl, g_xl);
    cudaGetSymbolAddress((void**)&pah, g_ah);
    cudaGetSymbolAddress((void**)&pal, g_al);
    cudaGetSymbolAddress((void**)&pwth, g_wth);
    cudaGetSymbolAddress((void**)&pwtl, g_wtl);

    cudaFuncSetAttribute(tgemm_mma, cudaFuncAttributeMaxDynamicSharedMemorySize, GM_SMEM);
    cudaFuncSetAttribute(att3, cudaFuncAttributeMaxDynamicSharedMemorySize, AT_SMEM);

    const size_t WSZ = (size_t)DD * DD;
    conv_split<<<(NROWS * DD / 4 + 255) / 256, 256>>>(
        (const float4*)x, (uint2*)pxh, (uint2*)pxl, NROWS * DD / 4);
    dim3 wgrid(DD / 32, DD / 32);
    // order matches fused epilogue: j = 0:q 1:k 2:v 3:p 4:g, 5:c
    trans_split<<<wgrid, 256>>>(Wq, pwth + 0 * WSZ, pwtl + 0 * WSZ);
    trans_split<<<wgrid, 256>>>(Wk, pwth + 1 * WSZ, pwtl + 1 * WSZ);
    trans_split<<<wgrid, 256>>>(Wv, pwth + 2 * WSZ, pwtl + 2 * WSZ);
    trans_split<<<wgrid, 256>>>(Wp, pwth + 3 * WSZ, pwtl + 3 * WSZ);
    trans_split<<<wgrid, 256>>>(Wg, pwth + 4 * WSZ, pwtl + 4 * WSZ);
    trans_split<<<wgrid, 256>>>(Wc, pwth + 5 * WSZ, pwtl + 5 * WSZ);
    clock_kernel<<<NROWS, 128>>>(x, Wcl);

    // fused projection GEMM: all 5 weight matrices in one launch (N = 10240)
    tgemm_mma<<<dim3(80, NROWS / 128), 256, GM_SMEM>>>(
        pxh, pxl, pwth, pwtl, (float*)nullptr, 1);

    scan_phase1<<<dim3(NC, BB * HH), 128>>>();
    scan_phase2<<<BB * HH, 128>>>();
    scan_phase3<<<dim3(NC, BB * HH), 128>>>();

    att3<<<dim3(TT / 128, BB * HH), 256, AT_SMEM>>>();

    tgemm_mma<<<dim3(DD / 128, NROWS / 128), 256, GM_SMEM>>>(
        pah, pal, pwth + 5 * WSZ, pwtl + 5 * WSZ, out, 0);
}